// round 16
// baseline (speedup 1.0000x reference)
#include <cuda_runtime.h>
#include <cuda_bf16.h>
#include <cstdint>

#define BATCH 64
#define SEQ   512
#define HID   1024
#define GATES 4096
#define NCTA  128
#define DIN   544
#define KX    1632   // 3*544: [Xhi|Xlo|Xhi] . [Whi|Whi|Wlo]  (proven 2.6e-4)

// ---------------- device-global scratch ------------------------------------
__device__ float          g_xproj[(size_t)SEQ * BATCH * GATES];
// per-CTA 131072 B contiguous, pre-swizzled: [Whi 32rows x 2048B | Wlo same]
__device__ __nv_bfloat16  g_w2[(size_t)NCTA * 65536];
// h: [buf][chunk q 0..7][row m 0..63][256B: hhi bf16, swizzled]
__device__ __nv_bfloat16  g_hq[2][65536];
__device__ __nv_bfloat16  g_xs[(size_t)BATCH * SEQ * KX];
__device__ __nv_bfloat16  g_ws[(size_t)GATES * KX];
__device__ unsigned       g_flag[8][32];     // per-128col-chunk producer counters

// ---------------- helpers ---------------------------------------------------
static __device__ __forceinline__ uint32_t smem_u32(const void* p) {
    uint32_t a;
    asm("{ .reg .u64 t; cvta.to.shared.u64 t, %1; cvt.u32.u64 %0, t; }" : "=r"(a) : "l"(p));
    return a;
}
static __device__ __forceinline__ void cp16(uint32_t dst, const void* src) {
    asm volatile("cp.async.cg.shared.global [%0], [%1], 16;" :: "r"(dst), "l"(src) : "memory");
}
#define CP_COMMIT() asm volatile("cp.async.commit_group;" ::: "memory")
#define CP_WAIT1()  asm volatile("cp.async.wait_group 1;" ::: "memory")
#define CP_WAIT0()  asm volatile("cp.async.wait_group 0;" ::: "memory")

static __device__ __forceinline__ void bulk_g2s(uint32_t dst, const void* src,
                                                uint32_t bytes, uint32_t mbar) {
    asm volatile(
        "cp.async.bulk.shared::cluster.global.mbarrier::complete_tx::bytes [%0], [%1], %2, [%3];"
        :: "r"(dst), "l"(src), "r"(bytes), "r"(mbar) : "memory");
}
#define MBAR_INIT(a, c) \
    asm volatile("mbarrier.init.shared.b64 [%0], %1;" :: "r"(a), "r"(c) : "memory")
#define MBAR_EXPECT(a, tx) \
    asm volatile("mbarrier.arrive.expect_tx.shared.b64 _, [%0], %1;" :: "r"(a), "r"(tx) : "memory")
#define MBAR_ARRIVE(a) \
    asm volatile("mbarrier.arrive.shared.b64 _, [%0];" :: "r"(a) : "memory")
#define MBAR_WAIT(a, p) do {                                                        \
    uint32_t _m = (a), _p = (p), _d;                                                \
    asm volatile("{\n\t.reg .pred q;\n\t"                                           \
        "mbarrier.try_wait.parity.acquire.cta.shared::cta.b64 q, [%1], %2;\n\t"     \
        "selp.b32 %0, 1, 0, q;\n\t}" : "=r"(_d) : "r"(_m), "r"(_p) : "memory");     \
    if (!_d) {                                                                      \
        asm volatile("{\n\t.reg .pred Q;\n\t"                                       \
            "W_%=:\n\t"                                                             \
            "mbarrier.try_wait.parity.acquire.cta.shared::cta.b64 Q, [%0], %1, 0x989680;\n\t" \
            "@Q bra.uni D_%=;\n\t"                                                  \
            "bra.uni W_%=;\n\t"                                                     \
            "D_%=:\n\t}" :: "r"(_m), "r"(_p) : "memory");                           \
    }                                                                               \
} while (0)

#define LDSM4(r0, r1, r2, r3, addr) \
    asm volatile("ldmatrix.sync.aligned.m8n8.x4.shared.b16 {%0,%1,%2,%3}, [%4];" \
        : "=r"(r0), "=r"(r1), "=r"(r2), "=r"(r3) : "r"(addr))

#define LDSM2(r0, r1, addr) \
    asm volatile("ldmatrix.sync.aligned.m8n8.x2.shared.b16 {%0,%1}, [%2];" \
        : "=r"(r0), "=r"(r1) : "r"(addr))

#define MMA16816(c, a0, a1, a2, a3, b0, b1) \
    asm volatile("mma.sync.aligned.m16n8k16.row.col.f32.bf16.bf16.f32 " \
        "{%0,%1,%2,%3}, {%4,%5,%6,%7}, {%8,%9}, {%0,%1,%2,%3};" \
        : "+f"((c)[0]), "+f"((c)[1]), "+f"((c)[2]), "+f"((c)[3]) \
        : "r"(a0), "r"(a1), "r"(a2), "r"(a3), "r"(b0), "r"(b1))

static __device__ __forceinline__ float sigmoidf_(float x) {
    return 1.0f / (1.0f + __expf(-x));
}
static __device__ __forceinline__ float tanhf_(float x) {
    return 2.0f / (1.0f + __expf(-2.0f * x)) - 1.0f;
}

// ---------------- init ------------------------------------------------------
__global__ void init_state() {
    int i = blockIdx.x * blockDim.x + threadIdx.x;
    if (i < 65536) g_hq[0][i] = __float2bfloat16(0.0f);
    if (i < 8) g_flag[i][0] = 0u;
}

// W_hh row g*HID+j -> reordered row r=4j+g, CTA slice cta=r>>5, pre-swizzled.
__global__ void wsplit(const float* __restrict__ W) {
    size_t idx = (size_t)blockIdx.x * 256 + threadIdx.x;
    if (idx >= (size_t)GATES * HID) return;
    int r = (int)(idx >> 10), k = (int)(idx & 1023);
    int j = r >> 2, g = r & 3;
    float v = W[(size_t)(g * HID + j) * HID + k];
    __nv_bfloat16 hi = __float2bfloat16(v);
    __nv_bfloat16 lo = __float2bfloat16(v - __bfloat162float(hi));
    int cta = r >> 5, rl = r & 31;
    int uu = k >> 3;
    int sw = (uu & ~7) | ((uu ^ rl) & 7);
    __nv_bfloat16* o = g_w2 + (size_t)cta * 65536;
    size_t e = (size_t)rl * 1024 + sw * 8 + (k & 7);
    o[e] = hi;
    o[32768 + e] = lo;
}

// X[m][k] -> g_xs[m] = [Xhi | Xlo | Xhi]
__global__ void xsplit(const float* __restrict__ X) {
    size_t idx = (size_t)blockIdx.x * 256 + threadIdx.x;
    if (idx >= (size_t)BATCH * SEQ * DIN) return;
    int m = (int)(idx / DIN), k = (int)(idx % DIN);
    float v = X[idx];
    __nv_bfloat16 hi = __float2bfloat16(v);
    __nv_bfloat16 lo = __float2bfloat16(v - __bfloat162float(hi));
    __nv_bfloat16* o = g_xs + (size_t)m * KX;
    o[k] = hi; o[DIN + k] = lo; o[2 * DIN + k] = hi;
}

// W_ih[n][k] -> g_ws[n] = [Whi | Whi | Wlo]
__global__ void wihsplit(const float* __restrict__ W) {
    size_t idx = (size_t)blockIdx.x * 256 + threadIdx.x;
    if (idx >= (size_t)GATES * DIN) return;
    int n = (int)(idx / DIN), k = (int)(idx % DIN);
    float v = W[idx];
    __nv_bfloat16 hi = __float2bfloat16(v);
    __nv_bfloat16 lo = __float2bfloat16(v - __bfloat162float(hi));
    __nv_bfloat16* o = g_ws + (size_t)n * KX;
    o[k] = hi; o[DIN + k] = hi; o[2 * DIN + k] = lo;
}

// ---------------- Phase 1: x_proj HMMA GEMM (K=1632, proven) ---------------
__global__ __launch_bounds__(256) void xproj_hmma(
    const float* __restrict__ bih, const float* __restrict__ bhh)
{
    __shared__ __align__(128) char xsm[4 * 10240];
    const uint32_t sb = smem_u32(xsm);
    const int tid = threadIdx.x, wid = tid >> 5, lane = tid & 31;
    const int n0 = blockIdx.x * 128, m0 = blockIdx.y * 128;
    const int wm = wid & 1, wn = wid >> 1;
    const int lrow = lane & 15, lk = lane >> 4;

    float c[4][4][4];
#pragma unroll
    for (int a = 0; a < 4; ++a)
#pragma unroll
        for (int b = 0; b < 4; ++b)
#pragma unroll
            for (int d = 0; d < 4; ++d) c[a][b][d] = 0.0f;

    auto loadAB = [&](int kc, int buf) {
        const int k0 = kc * 32;
        const uint32_t sA = sb + buf * 20480;
        const uint32_t sB = sA + 10240;
#pragma unroll
        for (int w = 0; w < 2; ++w) {
            int v = tid + 256 * w;
            int row = v >> 2, u = v & 3;
            cp16(sA + row * 80 + u * 16, g_xs + (size_t)(m0 + row) * KX + k0 + u * 8);
            cp16(sB + row * 80 + u * 16, g_ws + (size_t)(n0 + row) * KX + k0 + u * 8);
        }
        CP_COMMIT();
    };

    const int NKC = KX / 32;   // 51
    loadAB(0, 0);
    for (int kc = 0; kc < NKC; ++kc) {
        if (kc + 1 < NKC) { loadAB(kc + 1, (kc + 1) & 1); CP_WAIT1(); }
        else             { CP_WAIT0(); }
        __syncthreads();
        const uint32_t aBase = sb + (kc & 1) * 20480;
        const uint32_t bBase = aBase + 10240;
#pragma unroll
        for (int kt = 0; kt < 2; ++kt) {
            uint32_t A[4][4], Bq[2][4];
#pragma unroll
            for (int mt = 0; mt < 4; ++mt)
                LDSM4(A[mt][0], A[mt][1], A[mt][2], A[mt][3],
                      aBase + (64 * wm + 16 * mt + lrow) * 80 + kt * 32 + lk * 16);
#pragma unroll
            for (int ng = 0; ng < 2; ++ng)
                LDSM4(Bq[ng][0], Bq[ng][1], Bq[ng][2], Bq[ng][3],
                      bBase + (32 * wn + 16 * ng + lrow) * 80 + kt * 32 + lk * 16);
#pragma unroll
            for (int mt = 0; mt < 4; ++mt)
#pragma unroll
                for (int ng = 0; ng < 2; ++ng) {
                    MMA16816(c[mt][2 * ng],     A[mt][0], A[mt][1], A[mt][2], A[mt][3],
                             Bq[ng][0], Bq[ng][2]);
                    MMA16816(c[mt][2 * ng + 1], A[mt][0], A[mt][1], A[mt][2], A[mt][3],
                             Bq[ng][1], Bq[ng][3]);
                }
        }
        __syncthreads();
    }

    float2 bias[4];
#pragma unroll
    for (int nt = 0; nt < 4; ++nt) {
        int n = n0 + 32 * wn + 8 * nt + 2 * (lane & 3);
        bias[nt] = make_float2(bih[n] + bhh[n], bih[n + 1] + bhh[n + 1]);
    }
    const int r0 = m0 + 64 * wm + (lane >> 2);
#pragma unroll
    for (int mt = 0; mt < 4; ++mt) {
#pragma unroll
        for (int h = 0; h < 2; ++h) {
            int m = r0 + 16 * mt + 8 * h;
            int b = m >> 9, s = m & 511;
            float* orow = g_xproj + ((size_t)(s * BATCH + b)) * GATES;
#pragma unroll
            for (int nt = 0; nt < 4; ++nt) {
                int n = n0 + 32 * wn + 8 * nt + 2 * (lane & 3);
                *(float2*)(orow + n) = make_float2(c[mt][nt][2 * h] + bias[nt].x,
                                                   c[mt][nt][2 * h + 1] + bias[nt].y);
            }
        }
    }
}

// ---------------- Phase 2: persistent HMMA LSTM ----------------------------
// 16 warps = 2(M) x 8(N), warp tile 16x8, full K per warp. No per-chunk
// __syncthreads: consumed-mbarrier (16 warp arrivals) gates buffer reuse.
// smem:
//   [0, 131072)        W slice (hi +0, lo +65536), bulk-loaded once
//   [131072, 196608)   h ring: 2 x 32768 (chunk = 2 sub-chunks of 64rows x 256B)
//   [196608, 204928)   st[32][65] fp32 gate sums
//   [204928, 206976)   c slice [64 m][8 j]
//   [206976, 207040)   mbarriers: W, ringD0, ringD1, ringC0, ringC1
#define SM_W    0
#define SM_RING 131072
#define SM_ST   196608
#define SM_CS   204928
#define SM_MB   206976
#define SMEM_DYN 207104

__global__ __launch_bounds__(512, 1) void lstm_persistent(float* __restrict__ out) {
    extern __shared__ char smem[];
    const uint32_t sb = smem_u32(smem);
    const int tid = threadIdx.x, wid = tid >> 5, lane = tid & 31;
    const int jbase = blockIdx.x * 8;
    const int q0c = (blockIdx.x >> 5) & 3;   // rotation start = own 256-col chunk

    float (*st)[65] = (float (*)[65])(smem + SM_ST);
    float* cs = (float*)(smem + SM_CS);
    const uint32_t mbW  = sb + SM_MB;
    const uint32_t mbD0 = sb + SM_MB + 8;    // data-ready, per buffer
    const uint32_t mbC0 = sb + SM_MB + 24;   // consumed, per buffer (16 arrivals)

    if (tid == 0) {
        MBAR_INIT(mbW, 1);
        MBAR_INIT(mbD0, 1);
        MBAR_INIT(mbD0 + 8, 1);
        MBAR_INIT(mbC0, 16);
        MBAR_INIT(mbC0 + 8, 16);
    }
    __syncthreads();
    if (tid == 0) {
        MBAR_EXPECT(mbW, 131072u);
        bulk_g2s(sb + SM_W, g_w2 + (size_t)blockIdx.x * 65536, 131072u, mbW);
    }
    cs[tid] = 0.0f;
    MBAR_WAIT(mbW, 0u);
    __syncthreads();

    // warp mapping: mi = M 16-row block, ni = N 8-col block
    const int mi = wid & 1, ni = wid >> 1;
    const int lrow = lane & 15, lk = lane >> 4;
    const int arow = 16 * mi + lrow;
    const uint32_t aHi = sb + SM_W + arow * 2048;
    const uint32_t aLo = aHi + 65536;
    const int nrow = 8 * ni + (lane & 7);
    const int kh = (lane >> 3) & 1;
    const uint32_t bRow = sb + SM_RING + nrow * 256;

    const int ejl = tid & 7, em = tid >> 3;
    const int eq = jbase >> 7;
    const int ej7 = (jbase & 127) + ejl;
    const int eu = ej7 >> 3;
    const int esw = (eu & ~7) | ((eu ^ em) & 7);
    const size_t ebase = (size_t)eq * 8192 + (size_t)em * 128;

    unsigned dphase[2] = {0u, 0u};       // data mbar phases (all threads)
    unsigned cphase[2] = {0u, 0u};       // consumed mbar phases (tid0)
    unsigned issued[2] = {0u, 0u};       // issues per buffer (tid0)

    for (int t = 0; t < SEQ; ++t) {
        const __nv_bfloat16* __restrict__ hin = g_hq[t & 1];
        __nv_bfloat16* __restrict__ hq = g_hq[(t & 1) ^ 1];
        const float* __restrict__ xp = g_xproj + (size_t)t * BATCH * GATES;

        const int ej = jbase + ejl;
        const float* xr = xp + (size_t)em * GATES;
        float xg[4];
#pragma unroll
        for (int g = 0; g < 4; ++g) xg[g] = __ldg(xr + g * HID + ej);

        float c[4] = {0.f, 0.f, 0.f, 0.f};

        // issue i-th 256-col chunk: wait buffer consumed, wait producer flags, bulk
        auto issue_chunk = [&](int i) {
            if (tid == 0) {
                const int buf = i & 1;
                if (issued[buf] > 0u) {
                    MBAR_WAIT(mbC0 + buf * 8, cphase[buf]);
                    cphase[buf] ^= 1u;
                }
                issued[buf]++;
                const int q = (q0c + i) & 3;
                const unsigned tgt = 16u * (unsigned)t;
                unsigned v;
                do {
                    asm volatile("ld.acquire.gpu.global.u32 %0, [%1];"
                                 : "=r"(v) : "l"(&g_flag[2 * q][0]));
                } while (v < tgt);
                do {
                    asm volatile("ld.acquire.gpu.global.u32 %0, [%1];"
                                 : "=r"(v) : "l"(&g_flag[2 * q + 1][0]));
                } while (v < tgt);
                uint32_t mb = mbD0 + buf * 8;
                MBAR_EXPECT(mb, 32768u);
                bulk_g2s(sb + SM_RING + buf * 32768, hin + (size_t)q * 16384,
                         32768u, mb);
            }
        };

        issue_chunk(0);
        issue_chunk(1);

#pragma unroll 1
        for (int i = 0; i < 4; ++i) {
            const int q = (q0c + i) & 3;
            const int buf = i & 1;
            MBAR_WAIT(mbD0 + buf * 8, dphase[buf]);
            dphase[buf] ^= 1u;
#pragma unroll
            for (int qq = 0; qq < 2; ++qq) {
                const int qf = 2 * q + qq;
                const uint32_t bB = bRow + buf * 32768 + qq * 16384;
#pragma unroll
                for (int ks = 0; ks < 8; ++ks) {
                    int ub = 2 * ks + kh;
                    uint32_t baddr = bB + ((ub & ~7) | ((ub ^ nrow) & 7)) * 16;
                    uint32_t b0, b1;
                    LDSM2(b0, b1, baddr);
                    int ua = qf * 16 + 2 * ks + lk;
                    uint32_t off = ((ua & ~7) | ((ua ^ arow) & 7)) * 16;
                    uint32_t a0, a1, a2, a3;
                    LDSM4(a0, a1, a2, a3, aHi + off);
                    MMA16816(c, a0, a1, a2, a3, b0, b1);
                    LDSM4(a0, a1, a2, a3, aLo + off);
                    MMA16816(c, a0, a1, a2, a3, b0, b1);
                }
            }
            if (lane == 0) MBAR_ARRIVE(mbC0 + buf * 8);   // this warp done with buf
            if (i + 2 < 4) issue_chunk(i + 2);            // tid0 waits consumed, refills
        }

        // ---- stage C frags (single copy) ----
        {
            const int gid = lane >> 2, tig = lane & 3;
            const int r0 = 16 * mi + gid;
            const int c0 = 8 * ni + 2 * tig;
            st[r0][c0]         = c[0]; st[r0][c0 + 1]     = c[1];
            st[r0 + 8][c0]     = c[2]; st[r0 + 8][c0 + 1] = c[3];
        }
        __syncthreads();

        // ---- fused LSTM elementwise epilogue (1 thread = 1 (m,j)) ----
        {
            const int m = em;
            const int j = jbase + ejl;
            float gi = st[ejl * 4 + 0][m] + xg[0];
            float gf = st[ejl * 4 + 1][m] + xg[1];
            float gg = st[ejl * 4 + 2][m] + xg[2];
            float go = st[ejl * 4 + 3][m] + xg[3];
            float cold = cs[m * 8 + ejl];
            float cn = sigmoidf_(gf) * cold + sigmoidf_(gi) * tanhf_(gg);
            cs[m * 8 + ejl] = cn;
            float h = sigmoidf_(go) * tanhf_(cn);
            hq[ebase + esw * 8 + (ej7 & 7)] = __float2bfloat16(h);
            if (t == SEQ - 1) {
                out[(size_t)m * HID + j] = h;
                out[(size_t)BATCH * HID + (size_t)m * HID + j] = cn;
            }
        }

        // ---- signal chunk complete (producer flag) ----
        __threadfence();
        __syncthreads();
        if (tid == 0 && t < SEQ - 1) atomicAdd(&g_flag[eq][0], 1u);
    }
}

// ---------------- launch ---------------------------------------------------
extern "C" void kernel_launch(void* const* d_in, const int* in_sizes, int n_in,
                              void* d_out, int out_size) {
    const float* X   = (const float*)d_in[0];
    const float* Wih = (const float*)d_in[1];
    const float* Whh = (const float*)d_in[2];
    const float* bih = (const float*)d_in[3];
    const float* bhh = (const float*)d_in[4];
    float* out = (float*)d_out;

    static int configured = 0;
    if (!configured) {
        cudaFuncSetAttribute(lstm_persistent,
                             cudaFuncAttributeMaxDynamicSharedMemorySize, SMEM_DYN);
        configured = 1;
    }

    init_state<<<512, 256>>>();
    wsplit<<<(GATES * HID) / 256, 256>>>(Whh);
    xsplit<<<(BATCH * SEQ * DIN) / 256, 256>>>(X);
    wihsplit<<<(GATES * DIN) / 256, 256>>>(Wih);
    xproj_hmma<<<dim3(GATES / 128, (BATCH * SEQ) / 128), 256>>>(bih, bhh);
    lstm_persistent<<<NCTA, 512, SMEM_DYN>>>(out);
}

// round 17
// speedup vs baseline: 1.8826x; 1.8826x over previous
#include <cuda_runtime.h>
#include <cuda_bf16.h>
#include <cstdint>

#define BATCH 64
#define SEQ   512
#define HID   1024
#define GATES 4096
#define NCTA  128
#define DIN   544
#define KX    1632   // 3*544: [Xhi|Xlo|Xhi] . [Whi|Whi|Wlo]  (proven 2.6e-4)

// ---------------- device-global scratch ------------------------------------
__device__ float          g_xproj[(size_t)SEQ * BATCH * GATES];
// per-CTA 131072 B contiguous, pre-swizzled: [Whi 32rows x 2048B | Wlo same]
__device__ __nv_bfloat16  g_w2[(size_t)NCTA * 65536];
// h: [buf][chunk q 0..7][row m 0..63][256B: hhi bf16, swizzled]
__device__ __nv_bfloat16  g_hq[2][65536];
__device__ __nv_bfloat16  g_xs[(size_t)BATCH * SEQ * KX];
__device__ __nv_bfloat16  g_ws[(size_t)GATES * KX];
__device__ unsigned       g_flag[8][32];     // per-128col-chunk producer counters

// ---------------- helpers ---------------------------------------------------
static __device__ __forceinline__ uint32_t smem_u32(const void* p) {
    uint32_t a;
    asm("{ .reg .u64 t; cvta.to.shared.u64 t, %1; cvt.u32.u64 %0, t; }" : "=r"(a) : "l"(p));
    return a;
}
static __device__ __forceinline__ void cp16(uint32_t dst, const void* src) {
    asm volatile("cp.async.cg.shared.global [%0], [%1], 16;" :: "r"(dst), "l"(src) : "memory");
}
#define CP_COMMIT() asm volatile("cp.async.commit_group;" ::: "memory")
#define CP_WAIT1()  asm volatile("cp.async.wait_group 1;" ::: "memory")
#define CP_WAIT0()  asm volatile("cp.async.wait_group 0;" ::: "memory")

static __device__ __forceinline__ void bulk_g2s(uint32_t dst, const void* src,
                                                uint32_t bytes, uint32_t mbar) {
    asm volatile(
        "cp.async.bulk.shared::cluster.global.mbarrier::complete_tx::bytes [%0], [%1], %2, [%3];"
        :: "r"(dst), "l"(src), "r"(bytes), "r"(mbar) : "memory");
}
#define MBAR_INIT(a, c) \
    asm volatile("mbarrier.init.shared.b64 [%0], %1;" :: "r"(a), "r"(c) : "memory")
#define MBAR_EXPECT(a, tx) \
    asm volatile("mbarrier.arrive.expect_tx.shared.b64 _, [%0], %1;" :: "r"(a), "r"(tx) : "memory")
#define MBAR_WAIT(a, p) do {                                                        \
    uint32_t _m = (a), _p = (p), _d;                                                \
    asm volatile("{\n\t.reg .pred q;\n\t"                                           \
        "mbarrier.try_wait.parity.acquire.cta.shared::cta.b64 q, [%1], %2;\n\t"     \
        "selp.b32 %0, 1, 0, q;\n\t}" : "=r"(_d) : "r"(_m), "r"(_p) : "memory");     \
    if (!_d) {                                                                      \
        asm volatile("{\n\t.reg .pred Q;\n\t"                                       \
            "W_%=:\n\t"                                                             \
            "mbarrier.try_wait.parity.acquire.cta.shared::cta.b64 Q, [%0], %1, 0x989680;\n\t" \
            "@Q bra.uni D_%=;\n\t"                                                  \
            "bra.uni W_%=;\n\t"                                                     \
            "D_%=:\n\t}" :: "r"(_m), "r"(_p) : "memory");                           \
    }                                                                               \
} while (0)

#define LDSM4(r0, r1, r2, r3, addr) \
    asm volatile("ldmatrix.sync.aligned.m8n8.x4.shared.b16 {%0,%1,%2,%3}, [%4];" \
        : "=r"(r0), "=r"(r1), "=r"(r2), "=r"(r3) : "r"(addr))

#define MMA16816(c, a0, a1, a2, a3, b0, b1) \
    asm volatile("mma.sync.aligned.m16n8k16.row.col.f32.bf16.bf16.f32 " \
        "{%0,%1,%2,%3}, {%4,%5,%6,%7}, {%8,%9}, {%0,%1,%2,%3};" \
        : "+f"((c)[0]), "+f"((c)[1]), "+f"((c)[2]), "+f"((c)[3]) \
        : "r"(a0), "r"(a1), "r"(a2), "r"(a3), "r"(b0), "r"(b1))

static __device__ __forceinline__ float sigmoidf_(float x) {
    return 1.0f / (1.0f + __expf(-x));
}
static __device__ __forceinline__ float tanhf_(float x) {
    return 2.0f / (1.0f + __expf(-2.0f * x)) - 1.0f;
}

// ---------------- init ------------------------------------------------------
__global__ void init_state() {
    int i = blockIdx.x * blockDim.x + threadIdx.x;
    if (i < 65536) g_hq[0][i] = __float2bfloat16(0.0f);
    if (i < 8) g_flag[i][0] = 0u;
}

// W_hh row g*HID+j -> reordered row r=4j+g, CTA slice cta=r>>5, pre-swizzled.
__global__ void wsplit(const float* __restrict__ W) {
    size_t idx = (size_t)blockIdx.x * 256 + threadIdx.x;
    if (idx >= (size_t)GATES * HID) return;
    int r = (int)(idx >> 10), k = (int)(idx & 1023);
    int j = r >> 2, g = r & 3;
    float v = W[(size_t)(g * HID + j) * HID + k];
    __nv_bfloat16 hi = __float2bfloat16(v);
    __nv_bfloat16 lo = __float2bfloat16(v - __bfloat162float(hi));
    int cta = r >> 5, rl = r & 31;
    int uu = k >> 3;
    int sw = (uu & ~7) | ((uu ^ rl) & 7);
    __nv_bfloat16* o = g_w2 + (size_t)cta * 65536;
    size_t e = (size_t)rl * 1024 + sw * 8 + (k & 7);
    o[e] = hi;
    o[32768 + e] = lo;
}

// X[m][k] -> g_xs[m] = [Xhi | Xlo | Xhi]
__global__ void xsplit(const float* __restrict__ X) {
    size_t idx = (size_t)blockIdx.x * 256 + threadIdx.x;
    if (idx >= (size_t)BATCH * SEQ * DIN) return;
    int m = (int)(idx / DIN), k = (int)(idx % DIN);
    float v = X[idx];
    __nv_bfloat16 hi = __float2bfloat16(v);
    __nv_bfloat16 lo = __float2bfloat16(v - __bfloat162float(hi));
    __nv_bfloat16* o = g_xs + (size_t)m * KX;
    o[k] = hi; o[DIN + k] = lo; o[2 * DIN + k] = hi;
}

// W_ih[n][k] -> g_ws[n] = [Whi | Whi | Wlo]
__global__ void wihsplit(const float* __restrict__ W) {
    size_t idx = (size_t)blockIdx.x * 256 + threadIdx.x;
    if (idx >= (size_t)GATES * DIN) return;
    int n = (int)(idx / DIN), k = (int)(idx % DIN);
    float v = W[idx];
    __nv_bfloat16 hi = __float2bfloat16(v);
    __nv_bfloat16 lo = __float2bfloat16(v - __bfloat162float(hi));
    __nv_bfloat16* o = g_ws + (size_t)n * KX;
    o[k] = hi; o[DIN + k] = hi; o[2 * DIN + k] = lo;
}

// ---------------- Phase 1: x_proj HMMA GEMM (K=1632, proven) ---------------
__global__ __launch_bounds__(256) void xproj_hmma(
    const float* __restrict__ bih, const float* __restrict__ bhh)
{
    __shared__ __align__(128) char xsm[4 * 10240];
    const uint32_t sb = smem_u32(xsm);
    const int tid = threadIdx.x, wid = tid >> 5, lane = tid & 31;
    const int n0 = blockIdx.x * 128, m0 = blockIdx.y * 128;
    const int wm = wid & 1, wn = wid >> 1;
    const int lrow = lane & 15, lk = lane >> 4;

    float c[4][4][4];
#pragma unroll
    for (int a = 0; a < 4; ++a)
#pragma unroll
        for (int b = 0; b < 4; ++b)
#pragma unroll
            for (int d = 0; d < 4; ++d) c[a][b][d] = 0.0f;

    auto loadAB = [&](int kc, int buf) {
        const int k0 = kc * 32;
        const uint32_t sA = sb + buf * 20480;
        const uint32_t sB = sA + 10240;
#pragma unroll
        for (int w = 0; w < 2; ++w) {
            int v = tid + 256 * w;
            int row = v >> 2, u = v & 3;
            cp16(sA + row * 80 + u * 16, g_xs + (size_t)(m0 + row) * KX + k0 + u * 8);
            cp16(sB + row * 80 + u * 16, g_ws + (size_t)(n0 + row) * KX + k0 + u * 8);
        }
        CP_COMMIT();
    };

    const int NKC = KX / 32;   // 51
    loadAB(0, 0);
    for (int kc = 0; kc < NKC; ++kc) {
        if (kc + 1 < NKC) { loadAB(kc + 1, (kc + 1) & 1); CP_WAIT1(); }
        else             { CP_WAIT0(); }
        __syncthreads();
        const uint32_t aBase = sb + (kc & 1) * 20480;
        const uint32_t bBase = aBase + 10240;
#pragma unroll
        for (int kt = 0; kt < 2; ++kt) {
            uint32_t A[4][4], Bq[2][4];
#pragma unroll
            for (int mt = 0; mt < 4; ++mt)
                LDSM4(A[mt][0], A[mt][1], A[mt][2], A[mt][3],
                      aBase + (64 * wm + 16 * mt + lrow) * 80 + kt * 32 + lk * 16);
#pragma unroll
            for (int ng = 0; ng < 2; ++ng)
                LDSM4(Bq[ng][0], Bq[ng][1], Bq[ng][2], Bq[ng][3],
                      bBase + (32 * wn + 16 * ng + lrow) * 80 + kt * 32 + lk * 16);
#pragma unroll
            for (int mt = 0; mt < 4; ++mt)
#pragma unroll
                for (int ng = 0; ng < 2; ++ng) {
                    MMA16816(c[mt][2 * ng],     A[mt][0], A[mt][1], A[mt][2], A[mt][3],
                             Bq[ng][0], Bq[ng][2]);
                    MMA16816(c[mt][2 * ng + 1], A[mt][0], A[mt][1], A[mt][2], A[mt][3],
                             Bq[ng][1], Bq[ng][3]);
                }
        }
        __syncthreads();
    }

    float2 bias[4];
#pragma unroll
    for (int nt = 0; nt < 4; ++nt) {
        int n = n0 + 32 * wn + 8 * nt + 2 * (lane & 3);
        bias[nt] = make_float2(bih[n] + bhh[n], bih[n + 1] + bhh[n + 1]);
    }
    const int r0 = m0 + 64 * wm + (lane >> 2);
#pragma unroll
    for (int mt = 0; mt < 4; ++mt) {
#pragma unroll
        for (int h = 0; h < 2; ++h) {
            int m = r0 + 16 * mt + 8 * h;
            int b = m >> 9, s = m & 511;
            float* orow = g_xproj + ((size_t)(s * BATCH + b)) * GATES;
#pragma unroll
            for (int nt = 0; nt < 4; ++nt) {
                int n = n0 + 32 * wn + 8 * nt + 2 * (lane & 3);
                *(float2*)(orow + n) = make_float2(c[mt][nt][2 * h] + bias[nt].x,
                                                   c[mt][nt][2 * h + 1] + bias[nt].y);
            }
        }
    }
}

// ---------------- Phase 2: persistent HMMA LSTM (2-pass, 4x32KB chunks) ----
// smem:
//   [0, 131072)        W slice (hi +0, lo +65536), bulk-loaded once
//   [131072, 196608)   h ring: 2 x 32768 (chunk = 2 sub-chunks of 64rows x 256B)
//   [196608, 213248)   st[2][32][65] fp32 partial gate sums
//   [213248, 215296)   c slice [64 m][8 j]
//   [215296, 215360)   mbarriers: W, ring0, ring1
#define SM_W    0
#define SM_RING 131072
#define SM_ST   196608
#define SM_CS   213248
#define SM_MB   215296
#define SMEM_DYN 215360

__global__ __launch_bounds__(512, 1) void lstm_persistent(float* __restrict__ out) {
    extern __shared__ char smem[];
    const uint32_t sb = smem_u32(smem);
    const int tid = threadIdx.x, wid = tid >> 5, lane = tid & 31;
    const int jbase = blockIdx.x * 8;
    const int q0c = (blockIdx.x >> 5) & 3;   // rotation start = own 256-col chunk

    float (*st)[32][65] = (float (*)[32][65])(smem + SM_ST);
    float* cs = (float*)(smem + SM_CS);
    const uint32_t mbW  = sb + SM_MB;
    const uint32_t mbR0 = sb + SM_MB + 8;

    if (tid == 0) {
        MBAR_INIT(mbW, 1);
        MBAR_INIT(mbR0, 1);
        MBAR_INIT(mbR0 + 8, 1);
    }
    __syncthreads();
    if (tid == 0) {
        MBAR_EXPECT(mbW, 131072u);
        bulk_g2s(sb + SM_W, g_w2 + (size_t)blockIdx.x * 65536, 131072u, mbW);
    }
    cs[tid] = 0.0f;
    MBAR_WAIT(mbW, 0u);
    __syncthreads();

    // 16 warps = 2(M) x 4(N) x 2(Kg)
    const int mi = wid & 1, ni = (wid >> 1) & 3, kg = wid >> 3;
    const int lrow = lane & 15, lk = lane >> 4;
    const int arow = 16 * mi + lrow;
    const int brow = 16 * ni + lrow;
    const uint32_t aHi = sb + SM_W + arow * 2048;
    const uint32_t aLo = aHi + 65536;
    const uint32_t bRow0 = sb + SM_RING + brow * 256;

    const int ejl = tid & 7, em = tid >> 3;
    const int eq = jbase >> 7;
    const int ej7 = (jbase & 127) + ejl;
    const int eu = ej7 >> 3;
    const int esw = (eu & ~7) | ((eu ^ em) & 7);
    const size_t ebase = (size_t)eq * 8192 + (size_t)em * 128;

    unsigned pcnt[2] = {0u, 0u};

    for (int t = 0; t < SEQ; ++t) {
        const __nv_bfloat16* __restrict__ hin = g_hq[t & 1];
        __nv_bfloat16* __restrict__ hq = g_hq[(t & 1) ^ 1];
        const float* __restrict__ xp = g_xproj + (size_t)t * BATCH * GATES;

        const int ej = jbase + ejl;
        const float* xr = xp + (size_t)em * GATES;
        float xg[4];
#pragma unroll
        for (int g = 0; g < 4; ++g) xg[g] = __ldg(xr + g * HID + ej);

        float ca[4] = {0.f, 0.f, 0.f, 0.f};
        float cb[4] = {0.f, 0.f, 0.f, 0.f};

        // issue i-th 256-col chunk in rotation: wait both sub-flags, bulk copy 32KB
        auto issue_chunk = [&](int i) {
            if (tid == 0) {
                const int q = (q0c + i) & 3;
                const unsigned tgt = 16u * (unsigned)t;
                unsigned v;
                do {
                    asm volatile("ld.acquire.gpu.global.u32 %0, [%1];"
                                 : "=r"(v) : "l"(&g_flag[2 * q][0]));
                } while (v < tgt);
                do {
                    asm volatile("ld.acquire.gpu.global.u32 %0, [%1];"
                                 : "=r"(v) : "l"(&g_flag[2 * q + 1][0]));
                } while (v < tgt);
                uint32_t mb = mbR0 + (i & 1) * 8;
                MBAR_EXPECT(mb, 32768u);
                bulk_g2s(sb + SM_RING + (i & 1) * 32768, hin + (size_t)q * 16384,
                         32768u, mb);
            }
        };

        issue_chunk(0);
        issue_chunk(1);

#pragma unroll 1
        for (int i = 0; i < 4; ++i) {
            const int q = (q0c + i) & 3;
            const int buf = i & 1;
            MBAR_WAIT(mbR0 + buf * 8, pcnt[buf] & 1u);
            pcnt[buf]++;
#pragma unroll
            for (int qq = 0; qq < 2; ++qq) {
                const int qf = 2 * q + qq;
                const uint32_t bBase = bRow0 + buf * 32768 + qq * 16384;
                uint32_t Ah[4][4], Bh[4][4];
                // pass 1: Whi x hhi (cache A-hi and B-hi frags); warp's ks-half
#pragma unroll
                for (int ks = 0; ks < 4; ++ks) {
                    int ua = qf * 16 + 2 * (4 * kg + ks) + lk;
                    uint32_t aaddr = aHi + ((ua & ~7) | ((ua ^ arow) & 7)) * 16;
                    int ub = 2 * (4 * kg + ks) + lk;
                    uint32_t baddr = bBase + ((ub & ~7) | ((ub ^ brow) & 7)) * 16;
                    LDSM4(Ah[ks][0], Ah[ks][1], Ah[ks][2], Ah[ks][3], aaddr);
                    LDSM4(Bh[ks][0], Bh[ks][1], Bh[ks][2], Bh[ks][3], baddr);
                    MMA16816(ca, Ah[ks][0], Ah[ks][1], Ah[ks][2], Ah[ks][3], Bh[ks][0], Bh[ks][2]);
                    MMA16816(cb, Ah[ks][0], Ah[ks][1], Ah[ks][2], Ah[ks][3], Bh[ks][1], Bh[ks][3]);
                }
                // pass 2: Wlo x hhi (reuse cached B-hi frags)
#pragma unroll
                for (int ks = 0; ks < 4; ++ks) {
                    int ua = qf * 16 + 2 * (4 * kg + ks) + lk;
                    uint32_t aaddr = aLo + ((ua & ~7) | ((ua ^ arow) & 7)) * 16;
                    uint32_t l0, l1, l2, l3;
                    LDSM4(l0, l1, l2, l3, aaddr);
                    MMA16816(ca, l0, l1, l2, l3, Bh[ks][0], Bh[ks][2]);
                    MMA16816(cb, l0, l1, l2, l3, Bh[ks][1], Bh[ks][3]);
                }
            }
            // buffer-reuse guard only needed when a refill follows this step;
            // last two chunks are guarded by the staging+epilogue barriers.
            if (i + 2 < 4) {
                __syncthreads();
                issue_chunk(i + 2);
            }
        }

        // ---- stage partial C frags (per kg) ----
        {
            const int gid = lane >> 2, tig = lane & 3;
            const int r0 = 16 * mi + gid;
            const int c0 = 16 * ni + 2 * tig;
            st[kg][r0][c0]         = ca[0]; st[kg][r0][c0 + 1]     = ca[1];
            st[kg][r0 + 8][c0]     = ca[2]; st[kg][r0 + 8][c0 + 1] = ca[3];
            st[kg][r0][c0 + 8]     = cb[0]; st[kg][r0][c0 + 9]     = cb[1];
            st[kg][r0 + 8][c0 + 8] = cb[2]; st[kg][r0 + 8][c0 + 9] = cb[3];
        }
        __syncthreads();

        // ---- fused LSTM elementwise epilogue (1 thread = 1 (m,j)) ----
        {
            const int m = em;
            const int j = jbase + ejl;
            float gi = st[0][ejl * 4 + 0][m] + st[1][ejl * 4 + 0][m] + xg[0];
            float gf = st[0][ejl * 4 + 1][m] + st[1][ejl * 4 + 1][m] + xg[1];
            float gg = st[0][ejl * 4 + 2][m] + st[1][ejl * 4 + 2][m] + xg[2];
            float go = st[0][ejl * 4 + 3][m] + st[1][ejl * 4 + 3][m] + xg[3];
            float cold = cs[m * 8 + ejl];
            float cn = sigmoidf_(gf) * cold + sigmoidf_(gi) * tanhf_(gg);
            cs[m * 8 + ejl] = cn;
            float h = sigmoidf_(go) * tanhf_(cn);
            hq[ebase + esw * 8 + (ej7 & 7)] = __float2bfloat16(h);
            if (t == SEQ - 1) {
                out[(size_t)m * HID + j] = h;
                out[(size_t)BATCH * HID + (size_t)m * HID + j] = cn;
            }
        }

        // ---- signal chunk complete (producer flag) ----
        __threadfence();
        __syncthreads();
        if (tid == 0 && t < SEQ - 1) atomicAdd(&g_flag[eq][0], 1u);
    }
}

// ---------------- launch ---------------------------------------------------
extern "C" void kernel_launch(void* const* d_in, const int* in_sizes, int n_in,
                              void* d_out, int out_size) {
    const float* X   = (const float*)d_in[0];
    const float* Wih = (const float*)d_in[1];
    const float* Whh = (const float*)d_in[2];
    const float* bih = (const float*)d_in[3];
    const float* bhh = (const float*)d_in[4];
    float* out = (float*)d_out;

    static int configured = 0;
    if (!configured) {
        cudaFuncSetAttribute(lstm_persistent,
                             cudaFuncAttributeMaxDynamicSharedMemorySize, SMEM_DYN);
        configured = 1;
    }

    init_state<<<512, 256>>>();
    wsplit<<<(GATES * HID) / 256, 256>>>(Whh);
    xsplit<<<(BATCH * SEQ * DIN) / 256, 256>>>(X);
    wihsplit<<<(GATES * DIN) / 256, 256>>>(Wih);
    xproj_hmma<<<dim3(GATES / 128, (BATCH * SEQ) / 128), 256>>>(bih, bhh);
    lstm_persistent<<<NCTA, 512, SMEM_DYN>>>(out);
}